// round 8
// baseline (speedup 1.0000x reference)
#include <cuda_runtime.h>
#include <cuda_bf16.h>
#include <math.h>

#define Bsz 256
#define Tsz 512
#define Isz 128
#define Hsz 256
#define H2  512
#define NBLK 128
#define NTHR 256
#define KCH 64
#define PAD 65

// ---------------- static device scratch (no allocation) ----------------
__device__ float g_c[Bsz * Hsz];
__device__ float g_h[Bsz * Hsz];
__device__ float g_gru[Bsz * Hsz];
__device__ float g_a1[Bsz * H2];
__device__ float g_a2[Bsz * H2];
__device__ float g_n[Bsz];
__device__ float g_logit[Bsz];
__device__ unsigned g_cnt;
__device__ unsigned g_gen;

// ---------------- grid-wide barrier (all NBLK blocks co-resident) -------
__device__ __forceinline__ void grid_sync() {
    __syncthreads();
    if (threadIdx.x == 0) {
        __threadfence();
        unsigned gen = *((volatile unsigned*)&g_gen);
        if (atomicAdd(&g_cnt, 1u) == gridDim.x - 1u) {
            atomicExch(&g_cnt, 0u);
            __threadfence();
            atomicAdd(&g_gen, 1u);
        } else {
            while (*((volatile unsigned*)&g_gen) == gen) { __nanosleep(64); }
        }
        __threadfence();
    }
    __syncthreads();
}

__device__ __forceinline__ float dot4(const float* a, float4 w, float acc) {
    acc = fmaf(a[0], w.x, acc);
    acc = fmaf(a[1], w.y, acc);
    acc = fmaf(a[2], w.z, acc);
    return fmaf(a[3], w.w, acc);
}

// ---------------- MLP tile: rows [r0,r0+64), cols [j0,j0+16) ------------
// MODE 0: A[b*512+k] = Aa.   MODE 1 (concat): k<256 -> Aa[b*256+k],
//                                             k>=256 -> Asec[b*sstr + k-256]
// STORE 1: dst[b*512+j] = relu(acc).  STORE 0: reduce relu(acc) against W4
//          into s_part[row] (shared-mem atomics).
template <int MODE, int STORE>
__device__ __forceinline__ void mlp_stage(
    const float* __restrict__ Aa, const float* __restrict__ Asec, size_t sstr,
    const float* __restrict__ W, const float* __restrict__ bias,
    float* __restrict__ dst, const float* __restrict__ W4,
    float* sA, float* s_part, int r0, int j0, int tid)
{
    const int rl = (tid & 31) * 2;     // local row pair (lanes vary -> rows)
    const int j = j0 + (tid >> 5) * 2; // warp-uniform column pair
    float acc00 = bias[j], acc01 = bias[j + 1];
    float acc10 = acc00, acc11 = acc01;
    const float* wp0 = W + (size_t)j * H2;
    const float* wp1 = W + (size_t)(j + 1) * H2;

    for (int k0 = 0; k0 < H2; k0 += KCH) {
#pragma unroll
        for (int i = 0; i < (64 * KCH) / NTHR; i++) {
            int idx = tid + i * NTHR;
            int rr = idx >> 6;
            int kk = idx & 63;
            int k = k0 + kk;
            float v;
            if (MODE == 0) v = Aa[(size_t)(r0 + rr) * H2 + k];
            else v = (k < Hsz) ? Aa[(r0 + rr) * Hsz + k]
                               : Asec[(size_t)(r0 + rr) * sstr + (k - Hsz)];
            sA[rr * PAD + kk] = v;
        }
        __syncthreads();
        const float* a0 = sA + rl * PAD;
        const float* a1 = a0 + PAD;
#pragma unroll
        for (int kk = 0; kk < KCH; kk += 4) {
            float4 w0 = *(const float4*)(wp0 + k0 + kk);
            float4 w1 = *(const float4*)(wp1 + k0 + kk);
            acc00 = dot4(a0 + kk, w0, acc00);
            acc01 = dot4(a0 + kk, w1, acc01);
            acc10 = dot4(a1 + kk, w0, acc10);
            acc11 = dot4(a1 + kk, w1, acc11);
        }
        __syncthreads();
    }
    acc00 = fmaxf(acc00, 0.f); acc01 = fmaxf(acc01, 0.f);
    acc10 = fmaxf(acc10, 0.f); acc11 = fmaxf(acc11, 0.f);
    const int b0 = r0 + rl;
    if (STORE) {
        dst[(size_t)b0 * H2 + j] = acc00;
        dst[(size_t)b0 * H2 + j + 1] = acc01;
        dst[(size_t)(b0 + 1) * H2 + j] = acc10;
        dst[(size_t)(b0 + 1) * H2 + j + 1] = acc11;
    } else {
        float p0 = acc00 * W4[j] + acc01 * W4[j + 1];
        float p1 = acc10 * W4[j] + acc11 * W4[j + 1];
        atomicAdd(&s_part[rl], p0);
        atomicAdd(&s_part[rl + 1], p1);
    }
}

// ---------------- GRU tile: rows [r0,r0+64), out cols [jh0,jh0+8) -------
__device__ __forceinline__ void gru_stage(
    const float* __restrict__ Wih, const float* __restrict__ Whh,
    const float* __restrict__ bih, const float* __restrict__ bhh,
    float* sC, float* sH, int r0, int jh0, int tid,
    float* __restrict__ dst)
{
    const int rl = (tid & 31) * 2;
    const int jh = jh0 + (tid >> 5);   // warp-uniform output column
    float ir0 = bih[jh], iz0 = bih[jh + Hsz], in0 = bih[jh + 2 * Hsz];
    float hr0 = bhh[jh], hz0 = bhh[jh + Hsz], hn0 = bhh[jh + 2 * Hsz];
    float ir1 = ir0, iz1 = iz0, in1 = in0;
    float hr1 = hr0, hz1 = hz0, hn1 = hn0;
    const float* wr = Wih + (size_t)jh * Hsz;
    const float* wz = wr + (size_t)Hsz * Hsz;
    const float* wn = wz + (size_t)Hsz * Hsz;
    const float* vr = Whh + (size_t)jh * Hsz;
    const float* vz = vr + (size_t)Hsz * Hsz;
    const float* vn = vz + (size_t)Hsz * Hsz;

    for (int k0 = 0; k0 < Hsz; k0 += KCH) {
#pragma unroll
        for (int i = 0; i < (64 * KCH) / NTHR; i++) {
            int idx = tid + i * NTHR;
            int rr = idx >> 6;
            int kk = idx & 63;
            sC[rr * PAD + kk] = g_c[(r0 + rr) * Hsz + k0 + kk];
            sH[rr * PAD + kk] = g_h[(r0 + rr) * Hsz + k0 + kk];
        }
        __syncthreads();
        const float* c0 = sC + rl * PAD;
        const float* c1 = c0 + PAD;
        const float* h0 = sH + rl * PAD;
        const float* h1 = h0 + PAD;
#pragma unroll
        for (int kk = 0; kk < KCH; kk += 4) {
            float4 w_r = *(const float4*)(wr + k0 + kk);
            float4 w_z = *(const float4*)(wz + k0 + kk);
            float4 w_n = *(const float4*)(wn + k0 + kk);
            ir0 = dot4(c0 + kk, w_r, ir0);
            iz0 = dot4(c0 + kk, w_z, iz0);
            in0 = dot4(c0 + kk, w_n, in0);
            ir1 = dot4(c1 + kk, w_r, ir1);
            iz1 = dot4(c1 + kk, w_z, iz1);
            in1 = dot4(c1 + kk, w_n, in1);
            float4 v_r = *(const float4*)(vr + k0 + kk);
            float4 v_z = *(const float4*)(vz + k0 + kk);
            float4 v_n = *(const float4*)(vn + k0 + kk);
            hr0 = dot4(h0 + kk, v_r, hr0);
            hz0 = dot4(h0 + kk, v_z, hz0);
            hn0 = dot4(h0 + kk, v_n, hn0);
            hr1 = dot4(h1 + kk, v_r, hr1);
            hz1 = dot4(h1 + kk, v_z, hz1);
            hn1 = dot4(h1 + kk, v_n, hn1);
        }
        __syncthreads();
    }
    const int b0 = r0 + rl;
    float hv0 = g_h[b0 * Hsz + jh];
    float hv1 = g_h[(b0 + 1) * Hsz + jh];
    float rg0 = 1.f / (1.f + expf(-(ir0 + hr0)));
    float zg0 = 1.f / (1.f + expf(-(iz0 + hz0)));
    float ng0 = tanhf(in0 + rg0 * hn0);
    dst[(size_t)b0 * Hsz + jh] = (1.f - zg0) * ng0 + zg0 * hv0;
    float rg1 = 1.f / (1.f + expf(-(ir1 + hr1)));
    float zg1 = 1.f / (1.f + expf(-(iz1 + hz1)));
    float ng1 = tanhf(in1 + rg1 * hn1);
    dst[(size_t)(b0 + 1) * Hsz + jh] = (1.f - zg1) * ng1 + zg1 * hv1;
}

// ---------------- precompute c_concat = tanh(X @ W_cin^T) ---------------
__global__ void __launch_bounds__(NTHR) cin_kernel(
    const float* __restrict__ X, const float* __restrict__ Wc,
    const float* __restrict__ bc, float* __restrict__ outC)
{
    __shared__ float sA[64 * PAD];
    const int tid = threadIdx.x;
    const int blk = blockIdx.x;          // (B*T/64) rowgroups x 16 colgroups
    const int rg = blk >> 4, cg = blk & 15;
    const int r0 = rg * 64;
    const int rl = (tid & 31) * 2;
    const int j = cg * 16 + (tid >> 5) * 2;
    float acc00 = bc[j], acc01 = bc[j + 1];
    float acc10 = acc00, acc11 = acc01;
    const float* wp0 = Wc + (size_t)j * Isz;
    const float* wp1 = Wc + (size_t)(j + 1) * Isz;
    for (int k0 = 0; k0 < Isz; k0 += KCH) {
#pragma unroll
        for (int i = 0; i < (64 * KCH) / NTHR; i++) {
            int idx = tid + i * NTHR;
            int rr = idx >> 6;
            int kk = idx & 63;
            sA[rr * PAD + kk] = X[(size_t)(r0 + rr) * Isz + k0 + kk];
        }
        __syncthreads();
        const float* a0 = sA + rl * PAD;
        const float* a1 = a0 + PAD;
#pragma unroll
        for (int kk = 0; kk < KCH; kk += 4) {
            float4 w0 = *(const float4*)(wp0 + k0 + kk);
            float4 w1 = *(const float4*)(wp1 + k0 + kk);
            acc00 = dot4(a0 + kk, w0, acc00);
            acc01 = dot4(a0 + kk, w1, acc01);
            acc10 = dot4(a1 + kk, w0, acc10);
            acc11 = dot4(a1 + kk, w1, acc11);
        }
        __syncthreads();
    }
    const size_t m0 = (size_t)(r0 + rl);
    outC[m0 * Hsz + j] = tanhf(acc00);
    outC[m0 * Hsz + j + 1] = tanhf(acc01);
    outC[(m0 + 1) * Hsz + j] = tanhf(acc10);
    outC[(m0 + 1) * Hsz + j + 1] = tanhf(acc11);
}

// ---------------- persistent recurrent kernel ---------------------------
__global__ void __launch_bounds__(NTHR) rnn_kernel(
    const float* __restrict__ noise,
    const float* __restrict__ W1, const float* __restrict__ b1,
    const float* __restrict__ W2, const float* __restrict__ b2,
    const float* __restrict__ W3, const float* __restrict__ b3,
    const float* __restrict__ W4, const float* __restrict__ b4,
    const float* __restrict__ Wih, const float* __restrict__ Whh,
    const float* __restrict__ bih, const float* __restrict__ bhh,
    float* out)
{
    __shared__ float sA[64 * PAD];
    __shared__ float sB[64 * PAD];
    __shared__ float s_part[64];
    const int tid = threadIdx.x;
    const int blk = blockIdx.x;
    const int rg = blk >> 5, cg = blk & 31;
    const int r0 = rg * 64;
    const int j0 = cg * 16;
    const int jh0 = cg * 8;
    float* outC = out;
    float* outH = out + (size_t)Bsz * Tsz * Hsz;
    float* outF = outH + (size_t)Bsz * Tsz * Hsz;

    // init state (each block owns 2 batch rows)
    {
        int b = 2 * blk + (tid >> 7);
        int j2 = (tid & 127) * 2;
        g_c[b * Hsz + j2] = 0.f;
        g_c[b * Hsz + j2 + 1] = 0.f;
        g_h[b * Hsz + j2] = 0.f;
        g_h[b * Hsz + j2 + 1] = 0.f;
        if ((tid & 127) == 0) { g_n[b] = 0.f; g_logit[b] = b4[0]; }
    }
    grid_sync();

    for (int t = 0; t < Tsz; t++) {
        // -------- stage 1: a1 = relu([c, c_in] @ W1^T + b1), plus GRU ----
        mlp_stage<1, 1>(g_c, outC + (size_t)t * Hsz, (size_t)Tsz * Hsz,
                        W1, b1, g_a1, (const float*)0, sA, s_part, r0, j0, tid);
        gru_stage(Wih, Whh, bih, bhh, sA, sB, r0, jh0, tid, g_gru);
        grid_sync();
        // -------- stage 2: a2 --------------------------------------------
        mlp_stage<0, 1>(g_a1, (const float*)0, 0, W2, b2, g_a2,
                        (const float*)0, sA, s_part, r0, j0, tid);
        grid_sync();
        // -------- stage 3: a3 + logit reduction --------------------------
        if (tid < 64) s_part[tid] = 0.f;
        __syncthreads();
        mlp_stage<0, 0>(g_a2, (const float*)0, 0, W3, b3, (float*)0,
                        W4, sA, s_part, r0, j0, tid);
        __syncthreads();
        if (tid < 64) atomicAdd(&g_logit[r0 + tid], s_part[tid]);
        grid_sync();
        // -------- stage 4: gate + state update ---------------------------
        {
            int b = 2 * blk + (tid >> 7);
            float logit = g_logit[b];
            float u = noise[(size_t)t * Bsz + b];
            float lg = logf(u) - log1pf(-u);
            float alpha = 1.f / (1.f + expf(-(logit + lg) * 10.f));
            float oma = 1.f - alpha;
            float nold = g_n[b];
            float nnew = nold * oma + 1.f;
            float inv = 1.f / nnew;
            int j2 = (tid & 127) * 2;
#pragma unroll
            for (int q = 0; q < 2; q++) {
                int j = j2 + q;
                float cin = outC[(size_t)b * Tsz * Hsz + (size_t)t * Hsz + j];
                float cold = g_c[b * Hsz + j];
                float hold = g_h[b * Hsz + j];
                float gr = g_gru[b * Hsz + j];
                float hnew = hold * oma + alpha * gr;
                float cnew = (cold * nold * oma + cin) * inv;
                g_c[b * Hsz + j] = cnew;
                g_h[b * Hsz + j] = hnew;
                outH[(size_t)b * Tsz * Hsz + (size_t)t * Hsz + j] = hnew;
            }
            __syncthreads();
            if ((tid & 127) == 0) { g_n[b] = nnew; g_logit[b] = b4[0]; }
        }
        grid_sync();
    }
    // -------- h_final = GRUCell(c_T, h_T) --------------------------------
    gru_stage(Wih, Whh, bih, bhh, sA, sB, r0, jh0, tid, outF);
}

extern "C" void kernel_launch(void* const* d_in, const int* in_sizes, int n_in,
                              void* d_out, int out_size)
{
    const float* input = (const float*)d_in[0];
    const float* noise = (const float*)d_in[1];
    const float* W_cin = (const float*)d_in[2];
    const float* b_cin = (const float*)d_in[3];
    const float* W1 = (const float*)d_in[4];
    const float* b1 = (const float*)d_in[5];
    const float* W2 = (const float*)d_in[6];
    const float* b2 = (const float*)d_in[7];
    const float* W3 = (const float*)d_in[8];
    const float* b3 = (const float*)d_in[9];
    const float* W4 = (const float*)d_in[10];
    const float* b4 = (const float*)d_in[11];
    const float* Wih = (const float*)d_in[12];
    const float* Whh = (const float*)d_in[13];
    const float* bih = (const float*)d_in[14];
    const float* bhh = (const float*)d_in[15];
    float* out = (float*)d_out;

    // c_concat = tanh(input @ W_cin^T + b_cin), written straight into d_out
    cin_kernel<<<(Bsz * Tsz / 64) * (Hsz / 16), NTHR>>>(input, W_cin, b_cin, out);
    // persistent recurrent kernel (reads c_concat back as the c_in stream)
    rnn_kernel<<<NBLK, NTHR>>>(noise, W1, b1, W2, b2, W3, b3, W4, b4,
                               Wih, Whh, bih, bhh, out);
}

// round 9
// speedup vs baseline: 1.3565x; 1.3565x over previous
#include <cuda_runtime.h>
#include <cuda_bf16.h>
#include <math.h>

#define Bsz 256
#define Tsz 512
#define Isz 128
#define Hsz 256
#define H2  512
#define NBLK 128
#define NTHR 256
#define PAD 65

typedef unsigned long long u64;

// ---------------- static device scratch (no allocation) ----------------
__device__ float g_c[Bsz * Hsz];
__device__ float g_h[Bsz * Hsz];
__device__ float g_gru[Bsz * Hsz];
__device__ float g_a1[Bsz * H2];
__device__ float g_a2[Bsz * H2];
__device__ float g_n[Bsz];
__device__ float g_logit[Bsz];
__device__ unsigned g_cnt[4 * 32];   // one counter per rowgroup, 128B apart
__device__ unsigned g_gen[4 * 32];

// ---------------- f32x2 packed helpers ----------------------------------
__device__ __forceinline__ u64 pack2(float lo, float hi) {
    u64 r; asm("mov.b64 %0, {%1,%2};" : "=l"(r) : "f"(lo), "f"(hi)); return r;
}
__device__ __forceinline__ float sum2(u64 v) {
    float lo, hi; asm("mov.b64 {%0,%1}, %2;" : "=f"(lo), "=f"(hi) : "l"(v));
    return lo + hi;
}
__device__ __forceinline__ void fma2(u64& d, u64 a, u64 b) {
    asm("fma.rn.f32x2 %0, %1, %2, %0;" : "+l"(d) : "l"(a), "l"(b));
}

// ---------------- per-rowgroup barrier (32 co-resident blocks) -----------
__device__ __forceinline__ void rg_sync(int rg) {
    __syncthreads();
    if (threadIdx.x == 0) {
        __threadfence();
        unsigned* cnt = &g_cnt[rg * 32];
        unsigned* gen = &g_gen[rg * 32];
        unsigned g = *((volatile unsigned*)gen);
        if (atomicAdd(cnt, 1u) == 31u) {
            atomicExch(cnt, 0u);
            __threadfence();
            atomicAdd(gen, 1u);
        } else {
            while (*((volatile unsigned*)gen) == g) { __nanosleep(32); }
        }
        __threadfence();
    }
    __syncthreads();
}

// ---------------- chunk staging: 64 rows x 64 k, swizzled SMEM -----------
// SMEM word layout: row*64 + (k ^ (((row>>1)&15)<<1))  -> conflict-free LDS.64
__device__ __forceinline__ void ldg_chunk(float4* pre, const float* __restrict__ gsrc,
                                          size_t gstride, int r0, int k0, int tid) {
#pragma unroll
    for (int i = 0; i < 4; i++) {
        int q = tid + i * NTHR;           // float4 index 0..1023
        int row = q >> 4;
        int k = (q & 15) << 2;
        pre[i] = __ldcg((const float4*)(gsrc + (size_t)(r0 + row) * gstride + k0 + k));
    }
}
__device__ __forceinline__ void sts_chunk(float* sbuf, const float4* pre, int tid) {
#pragma unroll
    for (int i = 0; i < 4; i++) {
        int q = tid + i * NTHR;
        int row = q >> 4;
        unsigned k = (unsigned)((q & 15) << 2);
        unsigned swz = (((unsigned)row >> 1) & 15u) << 1;
        float* base = sbuf + row * 64;
        *(float2*)(base + (k ^ swz)) = make_float2(pre[i].x, pre[i].y);
        *(float2*)(base + ((k + 2u) ^ swz)) = make_float2(pre[i].z, pre[i].w);
    }
}

// ---------------- MLP compute for one 64-k chunk -------------------------
__device__ __forceinline__ void mlp_compute_chunk(
    const float* sbuf, const float* w0row, const float* w1row,
    int k0, int rl, unsigned swz,
    u64& acc00, u64& acc01, u64& acc10, u64& acc11)
{
    const float* a0 = sbuf + rl * 64;
    const float* a1 = a0 + 64;
#pragma unroll
    for (int kk = 0; kk < 64; kk += 4) {
        ulonglong2 w0 = *(const ulonglong2*)(w0row + k0 + kk);
        ulonglong2 w1 = *(const ulonglong2*)(w1row + k0 + kk);
        u64 a0a = *(const u64*)(a0 + ((unsigned)kk ^ swz));
        u64 a0b = *(const u64*)(a0 + (((unsigned)kk + 2u) ^ swz));
        u64 a1a = *(const u64*)(a1 + ((unsigned)kk ^ swz));
        u64 a1b = *(const u64*)(a1 + (((unsigned)kk + 2u) ^ swz));
        fma2(acc00, a0a, w0.x); fma2(acc00, a0b, w0.y);
        fma2(acc01, a0a, w1.x); fma2(acc01, a0b, w1.y);
        fma2(acc10, a1a, w0.x); fma2(acc10, a1b, w0.y);
        fma2(acc11, a1a, w1.x); fma2(acc11, a1b, w1.y);
    }
}

// ---------------- full MLP stage: 64 rows x 2x2 tile per thread ----------
// chunks c < splitc read (srcA, strA), else (srcB, strB).
template <int STORE>
__device__ __forceinline__ void mlp_stage(
    const float* __restrict__ srcA, size_t strA,
    const float* __restrict__ srcB, size_t strB, int splitc,
    const float* sW, const float* __restrict__ bias, const float* __restrict__ W4,
    float* __restrict__ dst, float* buf0, float* buf1, float* s_part,
    int r0, int j0, int tid)
{
    const int rl = (tid & 31) * 2;
    const int jl = (tid >> 5) * 2;
    const int j = j0 + jl;
    const unsigned swz = (((unsigned)rl >> 1) & 15u) << 1;
    const float* w0row = sW + (size_t)jl * H2;
    const float* w1row = w0row + H2;
    u64 acc00 = pack2(bias[j], 0.f);
    u64 acc01 = pack2(bias[j + 1], 0.f);
    u64 acc10 = acc00, acc11 = acc01;

    float4 pre[4];
    {
        const float* s = (0 < splitc) ? srcA : srcB;
        size_t st = (0 < splitc) ? strA : strB;
        ldg_chunk(pre, s, st, r0, 0, tid);
    }
#pragma unroll 1
    for (int c = 0; c < 8; c++) {
        float* cb = (c & 1) ? buf1 : buf0;
        sts_chunk(cb, pre, tid);
        if (c + 1 < 8) {
            const float* s = (c + 1 < splitc) ? srcA : srcB;
            size_t st = (c + 1 < splitc) ? strA : strB;
            ldg_chunk(pre, s, st, r0, (c + 1) * 64, tid);
        }
        __syncthreads();
        mlp_compute_chunk(cb, w0row, w1row, c * 64, rl, swz, acc00, acc01, acc10, acc11);
        __syncthreads();
    }
    float v00 = fmaxf(sum2(acc00), 0.f);
    float v01 = fmaxf(sum2(acc01), 0.f);
    float v10 = fmaxf(sum2(acc10), 0.f);
    float v11 = fmaxf(sum2(acc11), 0.f);
    const int b0 = r0 + rl;
    if (STORE) {
        *(float2*)(dst + (size_t)b0 * H2 + j) = make_float2(v00, v01);
        *(float2*)(dst + (size_t)(b0 + 1) * H2 + j) = make_float2(v10, v11);
    } else {
        float w4a = W4[j], w4b = W4[j + 1];
        atomicAdd(&s_part[rl], v00 * w4a + v01 * w4b);
        atomicAdd(&s_part[rl + 1], v10 * w4a + v11 * w4b);
    }
}

// ---------------- GRU stage: 64 rows x 1 col per thread (8 cols/block) ---
__device__ __forceinline__ void gru_stage(
    const float* sWih, const float* sWhh,
    const float* __restrict__ bih, const float* __restrict__ bhh,
    float* buf0, float* buf1, float* buf2, float* buf3,
    int r0, int jh0, int tid, float* __restrict__ dst)
{
    const int rl = (tid & 31) * 2;
    const int jl = (tid >> 5);
    const int jh = jh0 + jl;
    const unsigned swz = (((unsigned)rl >> 1) & 15u) << 1;
    const float* wr = sWih + (size_t)jl * Hsz;
    const float* wz = sWih + (size_t)(8 + jl) * Hsz;
    const float* wn = sWih + (size_t)(16 + jl) * Hsz;
    const float* vr = sWhh + (size_t)jl * Hsz;
    const float* vz = sWhh + (size_t)(8 + jl) * Hsz;
    const float* vn = sWhh + (size_t)(16 + jl) * Hsz;
    u64 ir0 = pack2(bih[jh], 0.f), iz0 = pack2(bih[jh + Hsz], 0.f), in0 = pack2(bih[jh + 2 * Hsz], 0.f);
    u64 hr0 = pack2(bhh[jh], 0.f), hz0 = pack2(bhh[jh + Hsz], 0.f), hn0 = pack2(bhh[jh + 2 * Hsz], 0.f);
    u64 ir1 = ir0, iz1 = iz0, in1 = in0;
    u64 hr1 = hr0, hz1 = hz0, hn1 = hn0;

    float4 prec[4], preh[4];
    ldg_chunk(prec, g_c, Hsz, r0, 0, tid);
    ldg_chunk(preh, g_h, Hsz, r0, 0, tid);
#pragma unroll 1
    for (int c = 0; c < 4; c++) {
        float* cb = (c & 1) ? buf1 : buf0;
        float* hb = (c & 1) ? buf3 : buf2;
        sts_chunk(cb, prec, tid);
        sts_chunk(hb, preh, tid);
        if (c + 1 < 4) {
            ldg_chunk(prec, g_c, Hsz, r0, (c + 1) * 64, tid);
            ldg_chunk(preh, g_h, Hsz, r0, (c + 1) * 64, tid);
        }
        __syncthreads();
        const float* c0 = cb + rl * 64;
        const float* c1 = c0 + 64;
        const float* h0 = hb + rl * 64;
        const float* h1 = h0 + 64;
        const int k0 = c * 64;
#pragma unroll
        for (int kk = 0; kk < 64; kk += 4) {
            ulonglong2 wrv = *(const ulonglong2*)(wr + k0 + kk);
            ulonglong2 wzv = *(const ulonglong2*)(wz + k0 + kk);
            ulonglong2 wnv = *(const ulonglong2*)(wn + k0 + kk);
            ulonglong2 vrv = *(const ulonglong2*)(vr + k0 + kk);
            ulonglong2 vzv = *(const ulonglong2*)(vz + k0 + kk);
            ulonglong2 vnv = *(const ulonglong2*)(vn + k0 + kk);
            u64 c0a = *(const u64*)(c0 + ((unsigned)kk ^ swz));
            u64 c0b = *(const u64*)(c0 + (((unsigned)kk + 2u) ^ swz));
            u64 c1a = *(const u64*)(c1 + ((unsigned)kk ^ swz));
            u64 c1b = *(const u64*)(c1 + (((unsigned)kk + 2u) ^ swz));
            u64 h0a = *(const u64*)(h0 + ((unsigned)kk ^ swz));
            u64 h0b = *(const u64*)(h0 + (((unsigned)kk + 2u) ^ swz));
            u64 h1a = *(const u64*)(h1 + ((unsigned)kk ^ swz));
            u64 h1b = *(const u64*)(h1 + (((unsigned)kk + 2u) ^ swz));
            fma2(ir0, c0a, wrv.x); fma2(ir0, c0b, wrv.y);
            fma2(iz0, c0a, wzv.x); fma2(iz0, c0b, wzv.y);
            fma2(in0, c0a, wnv.x); fma2(in0, c0b, wnv.y);
            fma2(ir1, c1a, wrv.x); fma2(ir1, c1b, wrv.y);
            fma2(iz1, c1a, wzv.x); fma2(iz1, c1b, wzv.y);
            fma2(in1, c1a, wnv.x); fma2(in1, c1b, wnv.y);
            fma2(hr0, h0a, vrv.x); fma2(hr0, h0b, vrv.y);
            fma2(hz0, h0a, vzv.x); fma2(hz0, h0b, vzv.y);
            fma2(hn0, h0a, vnv.x); fma2(hn0, h0b, vnv.y);
            fma2(hr1, h1a, vrv.x); fma2(hr1, h1b, vrv.y);
            fma2(hz1, h1a, vzv.x); fma2(hz1, h1b, vzv.y);
            fma2(hn1, h1a, vnv.x); fma2(hn1, h1b, vnv.y);
        }
        __syncthreads();
    }
    const int b0 = r0 + rl;
    float hv0 = __ldcg(&g_h[b0 * Hsz + jh]);
    float hv1 = __ldcg(&g_h[(b0 + 1) * Hsz + jh]);
    float R0 = 1.f / (1.f + expf(-(sum2(ir0) + sum2(hr0))));
    float Z0 = 1.f / (1.f + expf(-(sum2(iz0) + sum2(hz0))));
    float N0 = tanhf(sum2(in0) + R0 * sum2(hn0));
    dst[(size_t)b0 * Hsz + jh] = (1.f - Z0) * N0 + Z0 * hv0;
    float R1 = 1.f / (1.f + expf(-(sum2(ir1) + sum2(hr1))));
    float Z1 = 1.f / (1.f + expf(-(sum2(iz1) + sum2(hz1))));
    float N1 = tanhf(sum2(in1) + R1 * sum2(hn1));
    dst[(size_t)(b0 + 1) * Hsz + jh] = (1.f - Z1) * N1 + Z1 * hv1;
}

// ---------------- precompute c_concat = tanh(X @ W_cin^T) ----------------
__global__ void __launch_bounds__(NTHR) cin_kernel(
    const float* __restrict__ X, const float* __restrict__ Wc,
    const float* __restrict__ bc, float* __restrict__ outC)
{
    __shared__ float sA[64 * PAD];
    const int tid = threadIdx.x;
    const int blk = blockIdx.x;
    const int rg = blk >> 4, cg = blk & 15;
    const int r0 = rg * 64;
    const int rl = (tid & 31) * 2;
    const int j = cg * 16 + (tid >> 5) * 2;
    float acc00 = bc[j], acc01 = bc[j + 1];
    float acc10 = acc00, acc11 = acc01;
    const float* wp0 = Wc + (size_t)j * Isz;
    const float* wp1 = Wc + (size_t)(j + 1) * Isz;
    for (int k0 = 0; k0 < Isz; k0 += 64) {
#pragma unroll
        for (int i = 0; i < 16; i++) {
            int idx = tid + i * NTHR;
            int rr = idx >> 6;
            int kk = idx & 63;
            sA[rr * PAD + kk] = X[(size_t)(r0 + rr) * Isz + k0 + kk];
        }
        __syncthreads();
        const float* a0 = sA + rl * PAD;
        const float* a1 = a0 + PAD;
#pragma unroll
        for (int kk = 0; kk < 64; kk++) {
            float w0 = wp0[k0 + kk], w1 = wp1[k0 + kk];
            acc00 = fmaf(a0[kk], w0, acc00);
            acc01 = fmaf(a0[kk], w1, acc01);
            acc10 = fmaf(a1[kk], w0, acc10);
            acc11 = fmaf(a1[kk], w1, acc11);
        }
        __syncthreads();
    }
    const size_t m0 = (size_t)(r0 + rl);
    outC[m0 * Hsz + j] = tanhf(acc00);
    outC[m0 * Hsz + j + 1] = tanhf(acc01);
    outC[(m0 + 1) * Hsz + j] = tanhf(acc10);
    outC[(m0 + 1) * Hsz + j + 1] = tanhf(acc11);
}

// ---------------- persistent recurrent kernel ----------------------------
#define SMEM_FLOATS (3 * 16 * H2 + 2 * 24 * Hsz + 4 * 4096)
#define SMEM_BYTES (SMEM_FLOATS * 4)

__global__ void __launch_bounds__(NTHR, 1) rnn_kernel(
    const float* __restrict__ noise,
    const float* __restrict__ W1, const float* __restrict__ b1,
    const float* __restrict__ W2, const float* __restrict__ b2,
    const float* __restrict__ W3, const float* __restrict__ b3,
    const float* __restrict__ W4, const float* __restrict__ b4,
    const float* __restrict__ Wih, const float* __restrict__ Whh,
    const float* __restrict__ bih, const float* __restrict__ bhh,
    float* out)
{
    extern __shared__ float smem[];
    float* sW1 = smem;
    float* sW2 = sW1 + 16 * H2;
    float* sW3 = sW2 + 16 * H2;
    float* sWih = sW3 + 16 * H2;
    float* sWhh = sWih + 24 * Hsz;
    float* buf0 = sWhh + 24 * Hsz;
    float* buf1 = buf0 + 4096;
    float* buf2 = buf1 + 4096;
    float* buf3 = buf2 + 4096;
    __shared__ float s_part[64];

    const int tid = threadIdx.x;
    const int blk = blockIdx.x;
    const int rg = blk >> 5, cg = blk & 31;
    const int r0 = rg * 64;
    const int j0 = cg * 16;
    const int jh0 = cg * 8;
    float* outC = out;
    float* outH = out + (size_t)Bsz * Tsz * Hsz;
    float* outF = outH + (size_t)Bsz * Tsz * Hsz;

    // ---- preload this block's weight slices into SMEM (once) ----
    {
        const float* Wg[3] = {W1, W2, W3};
        float* sWd[3] = {sW1, sW2, sW3};
#pragma unroll 1
        for (int m = 0; m < 3; m++) {
            for (int i = tid; i < 2048; i += NTHR) {   // float4 count
                int col = i >> 7, k4 = i & 127;
                ((float4*)sWd[m])[col * 128 + k4] =
                    __ldg((const float4*)(Wg[m] + (size_t)(j0 + col) * H2) + k4);
            }
        }
        for (int i = tid; i < 1536; i += NTHR) {       // 24 rows x 64 f4
            int rr = i >> 6, k4 = i & 63;
            int gte = rr >> 3, cl = rr & 7;
            size_t grow = (size_t)(gte * Hsz + jh0 + cl) * Hsz;
            ((float4*)sWih)[rr * 64 + k4] = __ldg((const float4*)(Wih + grow) + k4);
            ((float4*)sWhh)[rr * 64 + k4] = __ldg((const float4*)(Whh + grow) + k4);
        }
    }

    // ---- init state (each block owns batch rows 2blk, 2blk+1) ----
    {
        int b = 2 * blk + (tid >> 7);
        int j2 = (tid & 127) * 2;
        *(float2*)(&g_c[b * Hsz + j2]) = make_float2(0.f, 0.f);
        *(float2*)(&g_h[b * Hsz + j2]) = make_float2(0.f, 0.f);
        if ((tid & 127) == 0) { g_n[b] = 0.f; g_logit[b] = b4[0]; }
    }
    rg_sync(rg);

    const size_t cstr = (size_t)Tsz * Hsz;
#pragma unroll 1
    for (int t = 0; t < Tsz; t++) {
        // ---- stage 1: a1 = relu([c, c_in] @ W1^T + b1)  +  GRU(c,h) ----
        mlp_stage<1>(g_c, (size_t)Hsz, outC + (size_t)t * Hsz - 256, cstr, 4,
                     sW1, b1, (const float*)0, g_a1, buf0, buf1, s_part, r0, j0, tid);
        gru_stage(sWih, sWhh, bih, bhh, buf0, buf1, buf2, buf3, r0, jh0, tid, g_gru);
        rg_sync(rg);
        // ---- stage 2: a2 ----
        mlp_stage<1>(g_a1, (size_t)H2, g_a1, (size_t)H2, 8,
                     sW2, b2, (const float*)0, g_a2, buf0, buf1, s_part, r0, j0, tid);
        rg_sync(rg);
        // ---- stage 3: a3 reduced against W4 -> logit ----
        if (tid < 64) s_part[tid] = 0.f;
        __syncthreads();
        mlp_stage<0>(g_a2, (size_t)H2, g_a2, (size_t)H2, 8,
                     sW3, b3, W4, (float*)0, buf0, buf1, s_part, r0, j0, tid);
        __syncthreads();
        if (tid < 64) atomicAdd(&g_logit[r0 + tid], s_part[tid]);
        rg_sync(rg);
        // ---- stage 4: gate + state update (own 2 batch rows) ----
        {
            int b = 2 * blk + (tid >> 7);
            float logit = __ldcg(&g_logit[b]);
            float u = noise[(size_t)t * Bsz + b];
            float lg = logf(u) - log1pf(-u);
            float alpha = 1.f / (1.f + expf(-(logit + lg) * 10.f));
            float oma = 1.f - alpha;
            float nold = g_n[b];
            float nnew = nold * oma + 1.f;
            float inv = 1.f / nnew;
            int j2 = (tid & 127) * 2;
            float2 cin = *(const float2*)(outC + (size_t)b * cstr + (size_t)t * Hsz + j2);
            float2 cold = *(const float2*)(&g_c[b * Hsz + j2]);
            float2 hold = *(const float2*)(&g_h[b * Hsz + j2]);
            float2 gr = __ldcg((const float2*)(&g_gru[b * Hsz + j2]));
            float2 hnew, cnew;
            hnew.x = hold.x * oma + alpha * gr.x;
            hnew.y = hold.y * oma + alpha * gr.y;
            cnew.x = (cold.x * nold * oma + cin.x) * inv;
            cnew.y = (cold.y * nold * oma + cin.y) * inv;
            *(float2*)(&g_c[b * Hsz + j2]) = cnew;
            *(float2*)(&g_h[b * Hsz + j2]) = hnew;
            *(float2*)(&outH[(size_t)b * cstr + (size_t)t * Hsz + j2]) = hnew;
            if ((tid & 127) == 0) { g_n[b] = nnew; g_logit[b] = b4[0]; }
        }
        rg_sync(rg);
    }
    // ---- h_final = GRUCell(c_T, h_T) ----
    gru_stage(sWih, sWhh, bih, bhh, buf0, buf1, buf2, buf3, r0, jh0, tid, outF);
}

extern "C" void kernel_launch(void* const* d_in, const int* in_sizes, int n_in,
                              void* d_out, int out_size)
{
    const float* input = (const float*)d_in[0];
    const float* noise = (const float*)d_in[1];
    const float* W_cin = (const float*)d_in[2];
    const float* b_cin = (const float*)d_in[3];
    const float* W1 = (const float*)d_in[4];
    const float* b1 = (const float*)d_in[5];
    const float* W2 = (const float*)d_in[6];
    const float* b2 = (const float*)d_in[7];
    const float* W3 = (const float*)d_in[8];
    const float* b3 = (const float*)d_in[9];
    const float* W4 = (const float*)d_in[10];
    const float* b4 = (const float*)d_in[11];
    const float* Wih = (const float*)d_in[12];
    const float* Whh = (const float*)d_in[13];
    const float* bih = (const float*)d_in[14];
    const float* bhh = (const float*)d_in[15];
    float* out = (float*)d_out;

    cudaFuncSetAttribute(rnn_kernel, cudaFuncAttributeMaxDynamicSharedMemorySize,
                         SMEM_BYTES);

    // c_concat = tanh(input @ W_cin^T + b_cin), written straight into d_out
    cin_kernel<<<(Bsz * Tsz / 64) * (Hsz / 16), NTHR>>>(input, W_cin, b_cin, out);
    // persistent recurrent kernel (reads c_concat back as the c_in stream)
    rnn_kernel<<<NBLK, NTHR, SMEM_BYTES>>>(noise, W1, b1, W2, b2, W3, b3, W4, b4,
                                           Wih, Whh, bih, bhh, out);
}